// round 3
// baseline (speedup 1.0000x reference)
#include <cuda_runtime.h>

// Problem-shape constants (fixed for this benchmark dataset).
#define NN 200000
#define EE 600000
#define CC 128
#define MAXP 8
#define TILE_M 32

// ---------------- scratch (static device globals; no allocation) ----------------
__device__ float g_xcur[(size_t)NN * CC];   // running x
__device__ float g_h0[(size_t)NN * CC];     // layer-0 output (involved rows only)
__device__ float g_agg[(size_t)NN * CC];    // per-(p,l) aggregation buffer
__device__ int g_eperiod[EE];               // period of each edge
__device__ int g_deg[MAXP * NN];            // per-period in-degree
__device__ unsigned char g_invl[MAXP * NN]; // involvement flags
__device__ int g_list[MAXP * NN];           // compacted involved-node lists
__device__ int g_cnt[MAXP];                 // list lengths

// ---------------- precompute: edge periods, degrees, involvement ----------------
__global__ void k_pre(const int* __restrict__ nt, const int* __restrict__ ei,
                      int n, int e, const int* __restrict__ minp,
                      const int* __restrict__ updp) {
    int i = blockIdx.x * blockDim.x + threadIdx.x;
    if (i >= e) return;
    int s = ei[i];
    int d = ei[e + i];
    int t = max(nt[s], nt[d]);
    int up = *updp; if (up < 1) up = 1;
    int p = (t - *minp) / up;
    if (p < 0) p = 0;
    if (p >= MAXP) p = MAXP - 1;
    g_eperiod[i] = p;
    atomicAdd(&g_deg[p * NN + d], 1);
    g_invl[p * NN + s] = 1;
    g_invl[p * NN + d] = 1;
}

// ---------------- compaction of involved nodes per period ----------------
__global__ void k_compact(int n) {
    int i = blockIdx.x * blockDim.x + threadIdx.x;
    int p = blockIdx.y;
    if (i >= n) return;
    if (g_invl[p * NN + i]) {
        int pos = atomicAdd(&g_cnt[p], 1);
        g_list[p * NN + pos] = i;
    }
}

// ---------------- zero agg rows of involved nodes ----------------
__global__ void k_zero(int p) {
    int idx = blockIdx.x * blockDim.x + threadIdx.x;
    int ni = idx >> 5;
    if (ni >= g_cnt[p]) return;
    int node = g_list[p * NN + ni];
    int c = (idx & 31) << 2;
    *(float4*)&g_agg[(size_t)node * CC + c] = make_float4(0.f, 0.f, 0.f, 0.f);
}

// ---------------- edge scatter: agg[dst] += h[src] for period-p edges ----------------
__global__ void k_scatter(const int* __restrict__ ei, const float* __restrict__ hin,
                          int e, int p) {
    int gi = blockIdx.x * blockDim.x + threadIdx.x;
    int w = gi >> 5;
    if (w >= e) return;
    if (g_eperiod[w] != p) return;
    int s = ei[w];
    int d = ei[e + w];
    int c = (gi & 31) << 2;
    float4 v = *(const float4*)&hin[(size_t)s * CC + c];
    float* a = &g_agg[(size_t)d * CC + c];
    atomicAdd(a + 0, v.x);
    atomicAdd(a + 1, v.y);
    atomicAdd(a + 2, v.z);
    atomicAdd(a + 3, v.w);
}

// ---------------- fused node update: [h|agg*invdeg] @ [Wr;Wn] + b, LN, (ReLU | x+=) ----
// Persistent blocks; weights (2*C*C fp32 = 128KB) staged once per block in smem.
// Thread tile: 4 nodes x 4 cols -> inner loop = 2x LDS.128 + 16 FFMA (FFMA-bound).
__global__ void __launch_bounds__(256, 1)
k_node(const float* __restrict__ hin, float* __restrict__ hout, float* __restrict__ xadd,
       const float* __restrict__ wr, const float* __restrict__ wn,
       const float* __restrict__ bias, const float* __restrict__ lng,
       const float* __restrict__ lnb, int p, int do_relu) {
    extern __shared__ float sm[];
    float* Wsh = sm;                 // [2*CC][CC]  = 32768 floats
    float* Vals = sm + 2 * CC * CC;  // [2*CC][TILE_M] = 8192 floats (reused as OutSh)
    __shared__ int s_node[TILE_M];
    __shared__ int s_valid[TILE_M];

    int cnt = g_cnt[p];
    int tid = threadIdx.x;

    // Stage concatenated weights: rows 0..127 = Wr[k][j], 128..255 = Wn[k][j]
    for (int i = tid; i < CC * CC; i += blockDim.x) {
        Wsh[i] = wr[i];
        Wsh[CC * CC + i] = wn[i];
    }

    int nb = (cnt + TILE_M - 1) / TILE_M;
    int tx = tid & 31;
    int ty = tid >> 5;
    int j0 = tx * 4;
    int m0 = ty * 4;

    for (int batch = blockIdx.x; batch < nb; batch += gridDim.x) {
        __syncthreads();  // weights ready (iter 0) / previous OutSh reads done
        int base = batch * TILE_M;

        // ---- stage values k-major: Vals[k][m] ----
        {
            int m = tid & 31;
            int kg = tid >> 5;  // 0..7, each covers 32 k
            int ni = base + m;
            int valid = (ni < cnt) ? 1 : 0;
            int node = g_list[p * NN + (valid ? ni : base)];
            if (kg == 0) { s_node[m] = node; s_valid[m] = valid; }
            int k0 = kg * 32;
            const float* srcrow;
            float scale;
            if (k0 < CC) {
                srcrow = hin + (size_t)node * CC + k0;
                scale = 1.0f;
            } else {
                srcrow = g_agg + (size_t)node * CC + (k0 - CC);
                scale = 1.0f / fmaxf((float)g_deg[p * NN + node], 1.0f);
            }
#pragma unroll
            for (int i = 0; i < 32; i += 4) {
                float4 v = *(const float4*)(srcrow + i);
                Vals[(k0 + i + 0) * TILE_M + m] = v.x * scale;
                Vals[(k0 + i + 1) * TILE_M + m] = v.y * scale;
                Vals[(k0 + i + 2) * TILE_M + m] = v.z * scale;
                Vals[(k0 + i + 3) * TILE_M + m] = v.w * scale;
            }
        }
        __syncthreads();

        // ---- GEMM: acc[mm][jj] = sum_k Vals[k][m0+mm] * Wsh[k][j0+jj] ----
        float acc[4][4];
#pragma unroll
        for (int a = 0; a < 4; a++)
#pragma unroll
            for (int b = 0; b < 4; b++) acc[a][b] = 0.f;

#pragma unroll 4
        for (int k = 0; k < 2 * CC; k++) {
            float4 w = *(const float4*)&Wsh[k * CC + j0];
            float4 v = *(const float4*)&Vals[k * TILE_M + m0];
            acc[0][0] += v.x * w.x; acc[0][1] += v.x * w.y;
            acc[0][2] += v.x * w.z; acc[0][3] += v.x * w.w;
            acc[1][0] += v.y * w.x; acc[1][1] += v.y * w.y;
            acc[1][2] += v.y * w.z; acc[1][3] += v.y * w.w;
            acc[2][0] += v.z * w.x; acc[2][1] += v.z * w.y;
            acc[2][2] += v.z * w.z; acc[2][3] += v.z * w.w;
            acc[3][0] += v.w * w.x; acc[3][1] += v.w * w.y;
            acc[3][2] += v.w * w.z; acc[3][3] += v.w * w.w;
        }

        float4 bv = *(const float4*)&bias[j0];
#pragma unroll
        for (int mm = 0; mm < 4; mm++) {
            acc[mm][0] += bv.x; acc[mm][1] += bv.y;
            acc[mm][2] += bv.z; acc[mm][3] += bv.w;
        }

        __syncthreads();  // all GEMM reads of Vals done; reuse as OutSh
        float* OutSh = Vals;  // [TILE_M][CC]
#pragma unroll
        for (int mm = 0; mm < 4; mm++)
            *(float4*)&OutSh[(m0 + mm) * CC + j0] =
                make_float4(acc[mm][0], acc[mm][1], acc[mm][2], acc[mm][3]);
        __syncthreads();

        // ---- LayerNorm: warp ty handles nodes ty*4 .. ty*4+3 ----
#pragma unroll
        for (int mm = 0; mm < 4; mm++) {
            int m_ = ty * 4 + mm;
            float vloc[4];
            float s1 = 0.f, s2 = 0.f;
#pragma unroll
            for (int i = 0; i < 4; i++) {
                float v = OutSh[m_ * CC + tx + i * 32];
                vloc[i] = v;
                s1 += v;
                s2 += v * v;
            }
#pragma unroll
            for (int off = 16; off > 0; off >>= 1) {
                s1 += __shfl_xor_sync(0xffffffffu, s1, off);
                s2 += __shfl_xor_sync(0xffffffffu, s2, off);
            }
            float mu = s1 * (1.0f / CC);
            float var = s2 * (1.0f / CC) - mu * mu;
            float rs = rsqrtf(var + 1e-5f);
            if (!s_valid[m_]) continue;
            int node = s_node[m_];
#pragma unroll
            for (int i = 0; i < 4; i++) {
                int j = tx + i * 32;
                float o = (vloc[i] - mu) * rs * lng[j] + lnb[j];
                if (do_relu) o = fmaxf(o, 0.f);
                if (xadd) xadd[(size_t)node * CC + j] += o;
                else      hout[(size_t)node * CC + j] = o;
            }
        }
    }
}

// ---------------- head: out[r][o] = x[r] . head_w[:,o] + head_b[o] ----------------
__global__ void k_head(const float* __restrict__ xc, const float* __restrict__ hw,
                       const float* __restrict__ hb, float* __restrict__ out,
                       int rows, int outc) {
    int r = blockIdx.x;
    int t = threadIdx.x;
    __shared__ float red[CC];
    for (int o = 0; o < outc; o++) {
        float v = xc[(size_t)r * CC + t] * hw[t * outc + o];
        red[t] = v;
        __syncthreads();
        for (int s = CC / 2; s > 0; s >>= 1) {
            if (t < s) red[t] += red[t + s];
            __syncthreads();
        }
        if (t == 0) out[r * outc + o] = red[0] + hb[o];
        __syncthreads();
    }
}

// ---------------- launch ----------------
extern "C" void kernel_launch(void* const* d_in, const int* in_sizes, int n_in,
                              void* d_out, int out_size) {
    const float* x         = (const float*)d_in[0];
    const int*   node_time = (const int*)d_in[1];
    const int*   edge_idx  = (const int*)d_in[2];
    const float* w_root    = (const float*)d_in[3];
    const float* w_nbr     = (const float*)d_in[4];
    const float* bias      = (const float*)d_in[5];
    const float* ln_g      = (const float*)d_in[6];
    const float* ln_b      = (const float*)d_in[7];
    const float* head_w    = (const float*)d_in[8];
    const float* head_b    = (const float*)d_in[9];
    const int*   mint      = (const int*)d_in[10];
    const int*   updp      = (const int*)d_in[12];

    int n    = in_sizes[1];
    int e    = in_sizes[2] / 2;
    int outc = in_sizes[9] > 0 ? in_sizes[9] : 1;
    int L    = in_sizes[5] / CC;
    int rows = out_size / outc;

    void *p_xcur, *p_h0, *p_deg, *p_invl, *p_cnt;
    cudaGetSymbolAddress(&p_xcur, g_xcur);
    cudaGetSymbolAddress(&p_h0, g_h0);
    cudaGetSymbolAddress(&p_deg, g_deg);
    cudaGetSymbolAddress(&p_invl, g_invl);
    cudaGetSymbolAddress(&p_cnt, g_cnt);

    size_t smem = (size_t)(2 * CC * CC + 2 * CC * TILE_M) * sizeof(float);  // 163840
    cudaFuncSetAttribute(k_node, cudaFuncAttributeMaxDynamicSharedMemorySize, (int)smem);

    cudaMemsetAsync(p_deg, 0, sizeof(int) * MAXP * NN, 0);
    cudaMemsetAsync(p_invl, 0, (size_t)MAXP * NN, 0);
    cudaMemsetAsync(p_cnt, 0, sizeof(int) * MAXP, 0);
    cudaMemcpyAsync(p_xcur, x, (size_t)n * CC * sizeof(float),
                    cudaMemcpyDeviceToDevice, 0);

    k_pre<<<(e + 255) / 256, 256>>>(node_time, edge_idx, n, e, mint, updp);
    dim3 gc((n + 255) / 256, MAXP);
    k_compact<<<gc, 256>>>(n);

    float* xcur = (float*)p_xcur;
    float* h0   = (float*)p_h0;

    int zgrid = (n * 32 + 255) / 256;
    long long sthreads = (long long)e * 32;
    unsigned sgrid = (unsigned)((sthreads + 255) / 256);

    for (int p = 0; p < MAXP; p++) {   // empty periods (cnt==0, no edges) no-op naturally
        for (int l = 0; l < L; l++) {
            const float* hin = (l == 0) ? xcur : h0;
            k_zero<<<zgrid, 256>>>(p);
            k_scatter<<<sgrid, 256>>>(edge_idx, hin, e, p);
            k_node<<<152, 256, smem>>>(hin, h0, (l == L - 1) ? xcur : (float*)0,
                                       w_root + (size_t)l * CC * CC,
                                       w_nbr + (size_t)l * CC * CC,
                                       bias + (size_t)l * CC,
                                       ln_g + (size_t)l * CC,
                                       ln_b + (size_t)l * CC,
                                       p, (l < L - 1) ? 1 : 0);
        }
    }

    k_head<<<rows, CC>>>(xcur, head_w, head_b, (float*)d_out, rows, outc);
}

// round 4
// speedup vs baseline: 1.6779x; 1.6779x over previous
#include <cuda_runtime.h>

// Problem-shape constants (fixed for this benchmark dataset).
#define NN 200000
#define EE 600000
#define CC 128
#define MAXP 8
#define TILE_M 64

// ---------------- scratch (static device globals; no allocation) ----------------
__device__ float g_xcur[(size_t)NN * CC];   // running x
__device__ float g_h0[(size_t)NN * CC];     // layer-0 output (involved rows only)
__device__ float g_agg[(size_t)NN * CC];    // per-(p,l) aggregation buffer
__device__ int g_deg[MAXP * NN];            // per-period in-degree
__device__ unsigned char g_invl[MAXP * NN]; // involvement flags
__device__ int g_list[MAXP * NN];           // compacted involved-node lists
__device__ int g_cnt[MAXP];                 // list lengths
__device__ int g_ebucket[MAXP * EE];        // per-period edge id lists
__device__ int g_ecnt[MAXP];                // edge list lengths

// ---------------- packed fp32x2 helpers (sm_103a FFMA2 path) ----------------
__device__ __forceinline__ unsigned long long pack2(float lo, float hi) {
    unsigned long long r;
    asm("mov.b64 %0, {%1, %2};" : "=l"(r) : "f"(lo), "f"(hi));
    return r;
}
__device__ __forceinline__ void unpack2(unsigned long long v, float& lo, float& hi) {
    asm("mov.b64 {%0, %1}, %2;" : "=f"(lo), "=f"(hi) : "l"(v));
}
__device__ __forceinline__ unsigned long long ffma2(unsigned long long a,
                                                    unsigned long long b,
                                                    unsigned long long c) {
    unsigned long long d;
    asm("fma.rn.f32x2 %0, %1, %2, %3;" : "=l"(d) : "l"(a), "l"(b), "l"(c));
    return d;
}

// ---------------- precompute: edge periods, degrees, involvement, buckets ----------------
__global__ void k_pre(const int* __restrict__ nt, const int* __restrict__ ei,
                      int n, int e, const int* __restrict__ minp,
                      const int* __restrict__ updp) {
    int i = blockIdx.x * blockDim.x + threadIdx.x;
    bool valid = i < e;
    int p = 0, s = 0, d = 0;
    if (valid) {
        s = ei[i];
        d = ei[e + i];
        int t = max(nt[s], nt[d]);
        int up = *updp; if (up < 1) up = 1;
        p = (t - *minp) / up;
        if (p < 0) p = 0;
        if (p >= MAXP) p = MAXP - 1;
    }
    unsigned act = __ballot_sync(0xffffffffu, valid);
    if (!valid) return;
    atomicAdd(&g_deg[p * NN + d], 1);
    g_invl[p * NN + s] = 1;
    g_invl[p * NN + d] = 1;
    // warp-aggregated append into period bucket (avoid same-address atomic storm)
    unsigned mask = __match_any_sync(act, p);
    int lane = threadIdx.x & 31;
    int leader = __ffs(mask) - 1;
    int pos = 0;
    if (lane == leader) pos = atomicAdd(&g_ecnt[p], __popc(mask));
    pos = __shfl_sync(mask, pos, leader);
    g_ebucket[p * EE + pos + __popc(mask & ((1u << lane) - 1))] = i;
}

// ---------------- compaction of involved nodes per period ----------------
__global__ void k_compact(int n) {
    int i = blockIdx.x * blockDim.x + threadIdx.x;
    int p = blockIdx.y;
    bool flag = (i < n) && g_invl[p * NN + i];
    unsigned m = __ballot_sync(0xffffffffu, flag);
    if (!flag) return;
    int lane = threadIdx.x & 31;
    int leader = __ffs(m) - 1;
    int pos = 0;
    if (lane == leader) pos = atomicAdd(&g_cnt[p], __popc(m));
    pos = __shfl_sync(m, pos, leader);
    g_list[p * NN + pos + __popc(m & ((1u << lane) - 1))] = i;
}

// ---------------- zero agg rows of involved nodes (persistent) ----------------
__global__ void k_zero(int p) {
    int cnt = g_cnt[p];
    int lane = threadIdx.x & 31;
    int wid = (blockIdx.x * blockDim.x + threadIdx.x) >> 5;
    int nw = (gridDim.x * blockDim.x) >> 5;
    for (int ni = wid; ni < cnt; ni += nw) {
        int node = g_list[p * NN + ni];
        *(float4*)&g_agg[(size_t)node * CC + (lane << 2)] =
            make_float4(0.f, 0.f, 0.f, 0.f);
    }
}

// ---------------- edge scatter: agg[dst] += h[src] for bucketed period-p edges ----------
__global__ void k_scatter(const int* __restrict__ ei, const float* __restrict__ hin,
                          int e, int p) {
    int cnt = g_ecnt[p];
    int lane = threadIdx.x & 31;
    int wid = (blockIdx.x * blockDim.x + threadIdx.x) >> 5;
    int nw = (gridDim.x * blockDim.x) >> 5;
    int c = lane << 2;
    for (int w = wid; w < cnt; w += nw) {
        int idx = g_ebucket[p * EE + w];
        int s = ei[idx];
        int d = ei[e + idx];
        float4 v = *(const float4*)&hin[(size_t)s * CC + c];
        float* a = &g_agg[(size_t)d * CC + c];
        asm volatile("red.global.add.v4.f32 [%0], {%1, %2, %3, %4};"
                     :: "l"(a), "f"(v.x), "f"(v.y), "f"(v.z), "f"(v.w)
                     : "memory");
    }
}

// ---------------- fused node update: [h|agg*invdeg] @ [Wr;Wn] + b, LN, (ReLU | x+=) ----
// Persistent blocks; concatenated weights (128KB) staged once per block in smem.
// Thread tile 4 nodes x 4 cols, inner loop in packed fp32x2 FFMA (8 FFMA2 / k).
__global__ void __launch_bounds__(512, 1)
k_node(const float* __restrict__ hin, float* __restrict__ hout, float* __restrict__ xadd,
       const float* __restrict__ wr, const float* __restrict__ wn,
       const float* __restrict__ bias, const float* __restrict__ lng,
       const float* __restrict__ lnb, int p, int do_relu) {
    extern __shared__ float sm[];
    float* Wsh = sm;                 // [2*CC][CC]      = 131072 B
    float* Vals = sm + 2 * CC * CC;  // [2*CC][TILE_M]  =  65536 B (reused as OutSh)
    __shared__ int s_node[TILE_M];
    __shared__ int s_valid[TILE_M];

    int cnt = g_cnt[p];
    if (cnt == 0) return;            // uniform early exit (empty period)
    int tid = threadIdx.x;

    // Stage concatenated weights: rows 0..127 = Wr[k][j], 128..255 = Wn[k][j]
    for (int i = tid; i < CC * CC; i += blockDim.x) {
        Wsh[i] = wr[i];
        Wsh[CC * CC + i] = wn[i];
    }

    int nb = (cnt + TILE_M - 1) / TILE_M;
    int tx = tid & 31;
    int ty = tid >> 5;          // 0..15
    int j0 = tx * 4;
    int m0 = ty * 4;

    for (int batch = blockIdx.x; batch < nb; batch += gridDim.x) {
        __syncthreads();  // weights ready (iter 0) / previous OutSh reads done
        int base = batch * TILE_M;

        // ---- stage values k-major: Vals[k][m], 512 threads = (m 0..63) x (kg 0..7) ----
        {
            int m = tid & 63;
            int kg = tid >> 6;  // 0..7, each covers 32 k
            int ni = base + m;
            int valid = (ni < cnt) ? 1 : 0;
            int node = g_list[p * NN + (valid ? ni : base)];
            if (kg == 0) { s_node[m] = node; s_valid[m] = valid; }
            int k0 = kg * 32;
            const float* srcrow;
            float scale;
            if (k0 < CC) {
                srcrow = hin + (size_t)node * CC + k0;
                scale = 1.0f;
            } else {
                srcrow = g_agg + (size_t)node * CC + (k0 - CC);
                scale = 1.0f / fmaxf((float)g_deg[p * NN + node], 1.0f);
            }
#pragma unroll
            for (int i = 0; i < 32; i += 4) {
                float4 v = *(const float4*)(srcrow + i);
                Vals[(k0 + i + 0) * TILE_M + m] = v.x * scale;
                Vals[(k0 + i + 1) * TILE_M + m] = v.y * scale;
                Vals[(k0 + i + 2) * TILE_M + m] = v.z * scale;
                Vals[(k0 + i + 3) * TILE_M + m] = v.w * scale;
            }
        }
        __syncthreads();

        // ---- GEMM via packed fp32x2: acc[mp][jj] holds rows (m0+2mp, m0+2mp+1) ----
        unsigned long long acc[2][4];
#pragma unroll
        for (int a = 0; a < 2; a++)
#pragma unroll
            for (int b = 0; b < 4; b++) acc[a][b] = 0ull;

#pragma unroll 4
        for (int k = 0; k < 2 * CC; k++) {
            float4 w = *(const float4*)&Wsh[k * CC + j0];
            double2 vd = *(const double2*)&Vals[k * TILE_M + m0];
            unsigned long long v01 = __double_as_longlong(vd.x);
            unsigned long long v23 = __double_as_longlong(vd.y);
            unsigned long long b;
            b = pack2(w.x, w.x);
            acc[0][0] = ffma2(v01, b, acc[0][0]);
            acc[1][0] = ffma2(v23, b, acc[1][0]);
            b = pack2(w.y, w.y);
            acc[0][1] = ffma2(v01, b, acc[0][1]);
            acc[1][1] = ffma2(v23, b, acc[1][1]);
            b = pack2(w.z, w.z);
            acc[0][2] = ffma2(v01, b, acc[0][2]);
            acc[1][2] = ffma2(v23, b, acc[1][2]);
            b = pack2(w.w, w.w);
            acc[0][3] = ffma2(v01, b, acc[0][3]);
            acc[1][3] = ffma2(v23, b, acc[1][3]);
        }

        float r[4][4];  // [mm][jj]
#pragma unroll
        for (int jj = 0; jj < 4; jj++) {
            unpack2(acc[0][jj], r[0][jj], r[1][jj]);
            unpack2(acc[1][jj], r[2][jj], r[3][jj]);
        }
        float4 bv = *(const float4*)&bias[j0];
#pragma unroll
        for (int mm = 0; mm < 4; mm++) {
            r[mm][0] += bv.x; r[mm][1] += bv.y;
            r[mm][2] += bv.z; r[mm][3] += bv.w;
        }

        __syncthreads();  // all GEMM reads of Vals done; reuse as OutSh
        float* OutSh = Vals;  // [TILE_M][CC]
#pragma unroll
        for (int mm = 0; mm < 4; mm++)
            *(float4*)&OutSh[(m0 + mm) * CC + j0] =
                make_float4(r[mm][0], r[mm][1], r[mm][2], r[mm][3]);
        __syncthreads();

        // ---- LayerNorm: warp ty handles nodes ty*4 .. ty*4+3 ----
#pragma unroll
        for (int mm = 0; mm < 4; mm++) {
            int m_ = ty * 4 + mm;
            float vloc[4];
            float s1 = 0.f, s2 = 0.f;
#pragma unroll
            for (int i = 0; i < 4; i++) {
                float v = OutSh[m_ * CC + tx + i * 32];
                vloc[i] = v;
                s1 += v;
                s2 += v * v;
            }
#pragma unroll
            for (int off = 16; off > 0; off >>= 1) {
                s1 += __shfl_xor_sync(0xffffffffu, s1, off);
                s2 += __shfl_xor_sync(0xffffffffu, s2, off);
            }
            float mu = s1 * (1.0f / CC);
            float var = s2 * (1.0f / CC) - mu * mu;
            float rs = rsqrtf(var + 1e-5f);
            if (!s_valid[m_]) continue;
            int node = s_node[m_];
#pragma unroll
            for (int i = 0; i < 4; i++) {
                int j = tx + i * 32;
                float o = (vloc[i] - mu) * rs * lng[j] + lnb[j];
                if (do_relu) o = fmaxf(o, 0.f);
                if (xadd) xadd[(size_t)node * CC + j] += o;
                else      hout[(size_t)node * CC + j] = o;
            }
        }
    }
}

// ---------------- head: out[r][o] = x[r] . head_w[:,o] + head_b[o] ----------------
__global__ void k_head(const float* __restrict__ xc, const float* __restrict__ hw,
                       const float* __restrict__ hb, float* __restrict__ out,
                       int rows, int outc) {
    int r = blockIdx.x;
    int t = threadIdx.x;
    __shared__ float red[CC];
    for (int o = 0; o < outc; o++) {
        float v = xc[(size_t)r * CC + t] * hw[t * outc + o];
        red[t] = v;
        __syncthreads();
        for (int s = CC / 2; s > 0; s >>= 1) {
            if (t < s) red[t] += red[t + s];
            __syncthreads();
        }
        if (t == 0) out[r * outc + o] = red[0] + hb[o];
        __syncthreads();
    }
}

// ---------------- launch ----------------
extern "C" void kernel_launch(void* const* d_in, const int* in_sizes, int n_in,
                              void* d_out, int out_size) {
    const float* x         = (const float*)d_in[0];
    const int*   node_time = (const int*)d_in[1];
    const int*   edge_idx  = (const int*)d_in[2];
    const float* w_root    = (const float*)d_in[3];
    const float* w_nbr     = (const float*)d_in[4];
    const float* bias      = (const float*)d_in[5];
    const float* ln_g      = (const float*)d_in[6];
    const float* ln_b      = (const float*)d_in[7];
    const float* head_w    = (const float*)d_in[8];
    const float* head_b    = (const float*)d_in[9];
    const int*   mint      = (const int*)d_in[10];
    const int*   updp      = (const int*)d_in[12];

    int n    = in_sizes[1];
    int e    = in_sizes[2] / 2;
    int outc = in_sizes[9] > 0 ? in_sizes[9] : 1;
    int L    = in_sizes[5] / CC;
    int rows = out_size / outc;

    void *p_xcur, *p_h0, *p_deg, *p_invl, *p_cnt, *p_ecnt;
    cudaGetSymbolAddress(&p_xcur, g_xcur);
    cudaGetSymbolAddress(&p_h0, g_h0);
    cudaGetSymbolAddress(&p_deg, g_deg);
    cudaGetSymbolAddress(&p_invl, g_invl);
    cudaGetSymbolAddress(&p_cnt, g_cnt);
    cudaGetSymbolAddress(&p_ecnt, g_ecnt);

    size_t smem = (size_t)(2 * CC * CC + 2 * CC * TILE_M) * sizeof(float);  // 196608
    cudaFuncSetAttribute(k_node, cudaFuncAttributeMaxDynamicSharedMemorySize, (int)smem);

    cudaMemsetAsync(p_deg, 0, sizeof(int) * MAXP * NN, 0);
    cudaMemsetAsync(p_invl, 0, (size_t)MAXP * NN, 0);
    cudaMemsetAsync(p_cnt, 0, sizeof(int) * MAXP, 0);
    cudaMemsetAsync(p_ecnt, 0, sizeof(int) * MAXP, 0);
    cudaMemcpyAsync(p_xcur, x, (size_t)n * CC * sizeof(float),
                    cudaMemcpyDeviceToDevice, 0);

    k_pre<<<(e + 255) / 256, 256>>>(node_time, edge_idx, n, e, mint, updp);
    dim3 gc((n + 255) / 256, MAXP);
    k_compact<<<gc, 256>>>(n);

    float* xcur = (float*)p_xcur;
    float* h0   = (float*)p_h0;

    for (int p = 0; p < MAXP; p++) {  // empty periods exit in a few us
        for (int l = 0; l < L; l++) {
            const float* hin = (l == 0) ? xcur : h0;
            k_zero<<<1216, 256>>>(p);
            k_scatter<<<1216, 256>>>(edge_idx, hin, e, p);
            k_node<<<152, 512, smem>>>(hin, h0, (l == L - 1) ? xcur : (float*)0,
                                       w_root + (size_t)l * CC * CC,
                                       w_nbr + (size_t)l * CC * CC,
                                       bias + (size_t)l * CC,
                                       ln_g + (size_t)l * CC,
                                       ln_b + (size_t)l * CC,
                                       p, (l < L - 1) ? 1 : 0);
        }
    }

    k_head<<<rows, CC>>>(xcur, head_w, head_b, (float*)d_out, rows, outc);
}